// round 3
// baseline (speedup 1.0000x reference)
#include <cuda_runtime.h>

#define NN 100000
#define EE 1600000

// ---------------- scratch (static __device__ globals; no allocations) --------
__device__ float g_dinv[NN];            // holds deg, then dinv
__device__ float g_nself[NN];           // dinv*dinv
__device__ float g_norme[EE];           // per-edge normalized weight
__device__ float g_bufA[(size_t)NN * 128];
__device__ float g_bufB[(size_t)NN * 128];

enum Buf { BA, BB };
template <Buf B> __device__ __forceinline__ float* bufp() {
    return (B == BA) ? g_bufA : g_bufB;
}

// ---------------- setup kernels ---------------------------------------------
__global__ void k_deg_init() {
    int i = blockIdx.x * blockDim.x + threadIdx.x;
    if (i < NN) g_dinv[i] = 1.0f;   // implicit self-loop weight
}

__global__ void k_deg(const int* __restrict__ ei, const float* __restrict__ w) {
    int e = blockIdx.x * blockDim.x + threadIdx.x;
    if (e < EE) {
        int c = ei[EE + e];          // col = target
        atomicAdd(g_dinv + c, w[e]);
    }
}

__global__ void k_dinv() {
    int i = blockIdx.x * blockDim.x + threadIdx.x;
    if (i < NN) {
        float d = rsqrtf(g_dinv[i]);   // g_dinv currently holds deg
        g_dinv[i] = d;
        g_nself[i] = d * d;
    }
}

__global__ void k_norme(const int* __restrict__ ei, const float* __restrict__ w) {
    int e = blockIdx.x * blockDim.x + threadIdx.x;
    if (e < EE) g_norme[e] = g_dinv[ei[e]] * w[e] * g_dinv[ei[EE + e]];
}

// ---------------- aggregation -----------------------------------------------
// out[i] = h[i] * nself[i] (+ bias)   -- initializes the accumulator
template <int F, bool BIAS, Buf HB, Buf OB, bool HX, bool OX>
__global__ void k_self_init(const float* __restrict__ hx, float* __restrict__ ox,
                            const float* __restrict__ bias) {
    constexpr int C = F / 4;
    int node = blockIdx.x * (256 / C) + threadIdx.x / C;
    int ch = threadIdx.x % C;
    if (node < NN) {
        const float* h = HX ? hx : bufp<HB>();
        float* out = OX ? ox : bufp<OB>();
        float s = g_nself[node];
        float4 v = *(const float4*)(h + (size_t)node * F + ch * 4);
        float4 o;
        if (BIAS) {
            float4 b = *(const float4*)(bias + ch * 4);
            o.x = v.x * s + b.x; o.y = v.y * s + b.y;
            o.z = v.z * s + b.z; o.w = v.w * s + b.w;
        } else {
            o.x = v.x * s; o.y = v.y * s; o.z = v.z * s; o.w = v.w * s;
        }
        *(float4*)(out + (size_t)node * F + ch * 4) = o;
    }
}

// out[col[e]] += h[row[e]] * norm_e[e]   (C threads per edge, float4 each)
template <int F, Buf HB, Buf OB, bool HX, bool OX>
__global__ void k_edge_agg(const int* __restrict__ ei,
                           const float* __restrict__ hx, float* __restrict__ ox) {
    constexpr int C = F / 4;
    int e = blockIdx.x * (256 / C) + threadIdx.x / C;
    int ch = threadIdx.x % C;
    if (e < EE) {
        const float* h = HX ? hx : bufp<HB>();
        float* out = OX ? ox : bufp<OB>();
        int r = ei[e];
        int c = ei[EE + e];
        float wv = g_norme[e];
        float4 v = __ldg((const float4*)(h + (size_t)r * F + ch * 4));
        float* o = out + (size_t)c * F + ch * 4;
        atomicAdd(o + 0, v.x * wv);
        atomicAdd(o + 1, v.y * wv);
        atomicAdd(o + 2, v.z * wv);
        atomicAdd(o + 3, v.w * wv);
    }
}

// ---------------- dense GEMM: C[N,OUT] = A[N,IN] @ W[IN,OUT] (+bias) ---------
template <int IN, int OUT, bool BIAS, Buf AB, Buf CB>
__global__ void k_gemm(const float* __restrict__ W, const float* __restrict__ bias) {
    constexpr int ROWS = 64;
    constexpr int Q = OUT / 4;
    const float* A = bufp<AB>();
    float* C = bufp<CB>();
    __shared__ float sW[IN * OUT];
    int t = threadIdx.x;
    for (int i = t; i < IN * OUT; i += 256) sW[i] = W[i];
    __syncthreads();

    int gr = blockIdx.x * ROWS + (t >> 2);
    int cg = t & 3;
    if (gr >= NN) return;

    float acc[Q];
#pragma unroll
    for (int j = 0; j < Q; j++) acc[j] = 0.f;

    const float4* a4 = (const float4*)(A + (size_t)gr * IN);
#pragma unroll 2
    for (int k0 = 0; k0 < IN / 4; k0++) {
        float4 a = __ldg(a4 + k0);
        float av[4] = {a.x, a.y, a.z, a.w};
#pragma unroll
        for (int kk = 0; kk < 4; kk++) {
            float aa = av[kk];
            const float* wr = sW + (k0 * 4 + kk) * OUT;
#pragma unroll
            for (int j = 0; j < Q; j++) {
                int c = ((j >> 2) << 4) + (cg << 2) + (j & 3);
                acc[j] += aa * wr[c];
            }
        }
    }

    float* cp = C + (size_t)gr * OUT;
#pragma unroll
    for (int jg = 0; jg < Q / 4; jg++) {
        int c0 = (jg << 4) + (cg << 2);
        float4 v;
        v.x = acc[jg * 4 + 0];
        v.y = acc[jg * 4 + 1];
        v.z = acc[jg * 4 + 2];
        v.w = acc[jg * 4 + 3];
        if (BIAS) {
            float4 b = *(const float4*)(bias + c0);
            v.x += b.x; v.y += b.y; v.z += b.z; v.w += b.w;
        }
        *(float4*)(cp + c0) = v;
    }
}

// ---------------- sigmoid (in-place on d_out) --------------------------------
__global__ void k_sigmoid(float4* __restrict__ out, int n4) {
    int i = blockIdx.x * blockDim.x + threadIdx.x;
    if (i < n4) {
        float4 v = out[i];
        v.x = 1.f / (1.f + __expf(-v.x));
        v.y = 1.f / (1.f + __expf(-v.y));
        v.z = 1.f / (1.f + __expf(-v.z));
        v.w = 1.f / (1.f + __expf(-v.w));
        out[i] = v;
    }
}

// ---------------- launch ------------------------------------------------------
extern "C" void kernel_launch(void* const* d_in, const int* in_sizes, int n_in,
                              void* d_out, int out_size) {
    const float* x  = (const float*)d_in[0];
    const int*   ei = (const int*)d_in[1];     // int32! (JAX downcasts int64)
    const float* w  = (const float*)d_in[2];
    const float* W1 = (const float*)d_in[3];
    const float* b1 = (const float*)d_in[4];
    const float* W2 = (const float*)d_in[5];
    const float* b2 = (const float*)d_in[6];
    const float* W3 = (const float*)d_in[7];
    const float* b3 = (const float*)d_in[8];
    float* out = (float*)d_out;

    const int T = 256;
    // --- normalization setup ---
    k_deg_init<<<(NN + T - 1) / T, T>>>();
    k_deg<<<(EE + T - 1) / T, T>>>(ei, w);
    k_dinv<<<(NN + T - 1) / T, T>>>();
    k_norme<<<(EE + T - 1) / T, T>>>(ei, w);

    // --- Layer 1: aggregate X (width 64) into bufA, GEMM 64->128 (+b1) -> bufB
    k_self_init<64, false, BA, BA, true, false><<<NN * 16 / T + 1, T>>>(x, nullptr, nullptr);
    k_edge_agg<64, BA, BA, true, false><<<EE * 16 / T, T>>>(ei, x, nullptr);
    k_gemm<64, 128, true, BA, BB><<<(NN + 63) / 64, T>>>(W1, b1);

    // --- Layer 2: GEMM 128->64 (bufB->bufA), aggregate width 64 (+b2) -> bufB
    k_gemm<128, 64, false, BB, BA><<<(NN + 63) / 64, T>>>(W2, nullptr);
    k_self_init<64, true, BA, BB, false, false><<<NN * 16 / T + 1, T>>>(nullptr, nullptr, b2);
    k_edge_agg<64, BA, BB, false, false><<<EE * 16 / T, T>>>(ei, nullptr, nullptr);

    // --- Layer 3: GEMM 64->32 (bufB->bufA), aggregate width 32 (+b3) -> d_out
    k_gemm<64, 32, false, BB, BA><<<(NN + 63) / 64, T>>>(W3, nullptr);
    k_self_init<32, true, BA, BA, false, true><<<NN * 8 / T + 1, T>>>(nullptr, out, b3);
    k_edge_agg<32, BA, BA, false, true><<<EE * 8 / T, T>>>(ei, nullptr, out);

    // --- sigmoid in place ---
    k_sigmoid<<<(NN * 32 / 4 + T - 1) / T, T>>>((float4*)out, NN * 32 / 4);
}

// round 4
// speedup vs baseline: 2.0192x; 2.0192x over previous
#include <cuda_runtime.h>

#define NN 100000
#define EE 1600000
#define NB 98   // ceil(NN/1024)

// ---------------- scratch (static __device__ globals) ------------------------
__device__ float g_dinv[NN];
__device__ float g_nself[NN];
__device__ int   g_cnt[NN];
__device__ int   g_incl[NN];
__device__ int   g_bsum[NB];
__device__ int   g_boff[NB];
__device__ int   g_rowptr[NN + 1];
__device__ int   g_cursor[NN];
__device__ int   g_csr_src[EE];
__device__ float g_csr_w[EE];
__device__ float g_bufA[(size_t)NN * 64];
__device__ float g_bufB[(size_t)NN * 128];

enum Buf { BA, BB };
template <Buf B> __device__ __forceinline__ float* bufp() {
    return (B == BA) ? g_bufA : g_bufB;
}

// ---------------- setup ------------------------------------------------------
__global__ void k_init() {
    int i = blockIdx.x * blockDim.x + threadIdx.x;
    if (i < NN) { g_dinv[i] = 1.0f; g_cnt[i] = 0; }
}

__global__ void k_deg(const int* __restrict__ ei, const float* __restrict__ w) {
    int e = blockIdx.x * blockDim.x + threadIdx.x;
    if (e < EE) {
        int c = ei[EE + e];
        atomicAdd(g_dinv + c, w[e]);
        atomicAdd(g_cnt + c, 1);
    }
}

__global__ void k_dinv() {
    int i = blockIdx.x * blockDim.x + threadIdx.x;
    if (i < NN) {
        float d = rsqrtf(g_dinv[i]);
        g_dinv[i] = d;
        g_nself[i] = d * d;
    }
}

// per-block inclusive scan of g_cnt
__global__ void k_scan1() {
    __shared__ int s[1024];
    int i = blockIdx.x * 1024 + threadIdx.x;
    int v = (i < NN) ? g_cnt[i] : 0;
    s[threadIdx.x] = v;
    __syncthreads();
    for (int d = 1; d < 1024; d <<= 1) {
        int t = (threadIdx.x >= d) ? s[threadIdx.x - d] : 0;
        __syncthreads();
        s[threadIdx.x] += t;
        __syncthreads();
    }
    if (i < NN) g_incl[i] = s[threadIdx.x];
    if (threadIdx.x == 1023) g_bsum[blockIdx.x] = s[1023];
}

// scan of block sums (single block)
__global__ void k_scan2() {
    __shared__ int s[128];
    int v = (threadIdx.x < NB) ? g_bsum[threadIdx.x] : 0;
    s[threadIdx.x] = v;
    __syncthreads();
    for (int d = 1; d < 128; d <<= 1) {
        int t = (threadIdx.x >= d) ? s[threadIdx.x - d] : 0;
        __syncthreads();
        s[threadIdx.x] += t;
        __syncthreads();
    }
    if (threadIdx.x < NB) g_boff[threadIdx.x] = s[threadIdx.x] - v;  // exclusive
}

__global__ void k_finalize() {
    int i = blockIdx.x * blockDim.x + threadIdx.x;
    if (i < NN) {
        int ex = g_incl[i] - g_cnt[i] + g_boff[i >> 10];
        g_rowptr[i] = ex;
        g_cursor[i] = ex;
    }
    if (i == 0) g_rowptr[NN] = EE;
}

// scatter edges into CSR with fused normalization
__global__ void k_scatter(const int* __restrict__ ei, const float* __restrict__ w) {
    int e = blockIdx.x * blockDim.x + threadIdx.x;
    if (e < EE) {
        int r = ei[e];
        int c = ei[EE + e];
        float ne = g_dinv[r] * w[e] * g_dinv[c];
        int pos = atomicAdd(g_cursor + c, 1);
        g_csr_src[pos] = r;
        g_csr_w[pos] = ne;
    }
}

// ---------------- CSR aggregation (gather, no atomics) -----------------------
// out[i] = sum_{e in in(i)} w_e * h[src_e] + nself[i]*h[i] (+bias) (sigmoid?)
template <int F, bool BIAS, bool SIG, Buf HB, Buf OB, bool HX, bool OX>
__global__ void k_agg(const float* __restrict__ hx, float* __restrict__ ox,
                      const float* __restrict__ bias) {
    constexpr int C = F / 4;               // lanes per node
    int node = blockIdx.x * (256 / C) + threadIdx.x / C;
    int ch = threadIdx.x % C;
    if (node >= NN) return;
    const float* h = HX ? hx : bufp<HB>();
    float* out = OX ? ox : bufp<OB>();

    int beg = g_rowptr[node];
    int end = g_rowptr[node + 1];
    float s = g_nself[node];
    float4 v = __ldg((const float4*)(h + (size_t)node * F + ch * 4));
    float ax = v.x * s, ay = v.y * s, az = v.z * s, aw = v.w * s;

    for (int j = beg; j < end; j++) {
        int src = g_csr_src[j];
        float wv = g_csr_w[j];
        float4 u = __ldg((const float4*)(h + (size_t)src * F + ch * 4));
        ax += u.x * wv; ay += u.y * wv; az += u.z * wv; aw += u.w * wv;
    }
    if (BIAS) {
        float4 b = *(const float4*)(bias + ch * 4);
        ax += b.x; ay += b.y; az += b.z; aw += b.w;
    }
    if (SIG) {
        ax = 1.f / (1.f + __expf(-ax));
        ay = 1.f / (1.f + __expf(-ay));
        az = 1.f / (1.f + __expf(-az));
        aw = 1.f / (1.f + __expf(-aw));
    }
    float4 o = {ax, ay, az, aw};
    *(float4*)(out + (size_t)node * F + ch * 4) = o;
}

// ---------------- dense GEMM: C[N,OUT] = A[N,IN] @ W[IN,OUT] (+bias) ---------
template <int IN, int OUT, bool BIAS, Buf AB, Buf CB>
__global__ void k_gemm(const float* __restrict__ W, const float* __restrict__ bias) {
    constexpr int ROWS = 64;
    constexpr int Q = OUT / 4;
    const float* A = bufp<AB>();
    float* C = bufp<CB>();
    __shared__ float sW[IN * OUT];
    int t = threadIdx.x;
    for (int i = t; i < IN * OUT; i += 256) sW[i] = W[i];
    __syncthreads();

    int gr = blockIdx.x * ROWS + (t >> 2);
    int cg = t & 3;
    if (gr >= NN) return;

    float acc[Q];
#pragma unroll
    for (int j = 0; j < Q; j++) acc[j] = 0.f;

    const float4* a4 = (const float4*)(A + (size_t)gr * IN);
#pragma unroll 2
    for (int k0 = 0; k0 < IN / 4; k0++) {
        float4 a = __ldg(a4 + k0);
        float av[4] = {a.x, a.y, a.z, a.w};
#pragma unroll
        for (int kk = 0; kk < 4; kk++) {
            float aa = av[kk];
            const float* wr = sW + (k0 * 4 + kk) * OUT;
#pragma unroll
            for (int j = 0; j < Q; j++) {
                int c = ((j >> 2) << 4) + (cg << 2) + (j & 3);
                acc[j] += aa * wr[c];
            }
        }
    }

    float* cp = C + (size_t)gr * OUT;
#pragma unroll
    for (int jg = 0; jg < Q / 4; jg++) {
        int c0 = (jg << 4) + (cg << 2);
        float4 v;
        v.x = acc[jg * 4 + 0];
        v.y = acc[jg * 4 + 1];
        v.z = acc[jg * 4 + 2];
        v.w = acc[jg * 4 + 3];
        if (BIAS) {
            float4 b = *(const float4*)(bias + c0);
            v.x += b.x; v.y += b.y; v.z += b.z; v.w += b.w;
        }
        *(float4*)(cp + c0) = v;
    }
}

// ---------------- launch ------------------------------------------------------
extern "C" void kernel_launch(void* const* d_in, const int* in_sizes, int n_in,
                              void* d_out, int out_size) {
    const float* x  = (const float*)d_in[0];
    const int*   ei = (const int*)d_in[1];     // int32 (JAX downcasts int64)
    const float* w  = (const float*)d_in[2];
    const float* W1 = (const float*)d_in[3];
    const float* b1 = (const float*)d_in[4];
    const float* W2 = (const float*)d_in[5];
    const float* b2 = (const float*)d_in[6];
    const float* W3 = (const float*)d_in[7];
    const float* b3 = (const float*)d_in[8];
    float* out = (float*)d_out;

    const int T = 256;
    // --- normalization + CSR build ---
    k_init<<<(NN + T - 1) / T, T>>>();
    k_deg<<<(EE + T - 1) / T, T>>>(ei, w);
    k_dinv<<<(NN + T - 1) / T, T>>>();
    k_scan1<<<NB, 1024>>>();
    k_scan2<<<1, 128>>>();
    k_finalize<<<(NN + T - 1) / T, T>>>();
    k_scatter<<<(EE + T - 1) / T, T>>>(ei, w);

    // --- Layer 1: aggregate X (width 64) -> bufA, GEMM 64->128 (+b1) -> bufB
    k_agg<64, false, false, BA, BA, true, false><<<NN * 16 / T + 1, T>>>(x, nullptr, nullptr);
    k_gemm<64, 128, true, BA, BB><<<(NN + 63) / 64, T>>>(W1, b1);

    // --- Layer 2: GEMM 128->64 (bufB->bufA), aggregate (+b2) -> bufB
    k_gemm<128, 64, false, BB, BA><<<(NN + 63) / 64, T>>>(W2, nullptr);
    k_agg<64, true, false, BA, BB, false, false><<<NN * 16 / T + 1, T>>>(nullptr, nullptr, b2);

    // --- Layer 3: GEMM 64->32 (bufB->bufA), aggregate (+b3, sigmoid) -> d_out
    k_gemm<64, 32, false, BB, BA><<<(NN + 63) / 64, T>>>(W3, nullptr);
    k_agg<32, true, true, BA, BA, false, true><<<NN * 8 / T + 1, T>>>(nullptr, out, b3);
}

// round 5
// speedup vs baseline: 2.7667x; 1.3702x over previous
#include <cuda_runtime.h>

#define NN 100000
#define EE 1600000
#define NB 98   // ceil(NN/1024)

// ---------------- scratch (static __device__ globals) ------------------------
__device__ float g_dinv[NN];
__device__ float g_nself[NN];
__device__ int   g_cnt[NN];
__device__ int   g_incl[NN];
__device__ int   g_bsum[NB];
__device__ int   g_boff[NB];
__device__ int   g_rowptr[NN + 1];
__device__ int   g_cursor[NN];
__device__ int   g_csr_src[EE];
__device__ float g_csr_w[EE];
__device__ float g_bufA[(size_t)NN * 64];
__device__ float g_bufB[(size_t)NN * 128];

enum Buf { BA, BB };
template <Buf B> __device__ __forceinline__ float* bufp() {
    return (B == BA) ? g_bufA : g_bufB;
}

// ---------------- setup ------------------------------------------------------
__global__ void k_init() {
    int i = blockIdx.x * blockDim.x + threadIdx.x;
    if (i < NN) { g_dinv[i] = 1.0f; g_cnt[i] = 0; }
}

__global__ void k_deg(const int* __restrict__ ei, const float* __restrict__ w) {
    int e = blockIdx.x * blockDim.x + threadIdx.x;
    if (e < EE) {
        int c = ei[EE + e];
        atomicAdd(g_dinv + c, w[e]);
        atomicAdd(g_cnt + c, 1);
    }
}

__global__ void k_dinv() {
    int i = blockIdx.x * blockDim.x + threadIdx.x;
    if (i < NN) {
        float d = rsqrtf(g_dinv[i]);
        g_dinv[i] = d;
        g_nself[i] = d * d;
    }
}

// per-block inclusive scan of g_cnt
__global__ void k_scan1() {
    __shared__ int s[1024];
    int i = blockIdx.x * 1024 + threadIdx.x;
    int v = (i < NN) ? g_cnt[i] : 0;
    s[threadIdx.x] = v;
    __syncthreads();
    for (int d = 1; d < 1024; d <<= 1) {
        int t = (threadIdx.x >= d) ? s[threadIdx.x - d] : 0;
        __syncthreads();
        s[threadIdx.x] += t;
        __syncthreads();
    }
    if (i < NN) g_incl[i] = s[threadIdx.x];
    if (threadIdx.x == 1023) g_bsum[blockIdx.x] = s[1023];
}

__global__ void k_scan2() {
    __shared__ int s[128];
    int v = (threadIdx.x < NB) ? g_bsum[threadIdx.x] : 0;
    s[threadIdx.x] = v;
    __syncthreads();
    for (int d = 1; d < 128; d <<= 1) {
        int t = (threadIdx.x >= d) ? s[threadIdx.x - d] : 0;
        __syncthreads();
        s[threadIdx.x] += t;
        __syncthreads();
    }
    if (threadIdx.x < NB) g_boff[threadIdx.x] = s[threadIdx.x] - v;  // exclusive
}

__global__ void k_finalize() {
    int i = blockIdx.x * blockDim.x + threadIdx.x;
    if (i < NN) {
        int ex = g_incl[i] - g_cnt[i] + g_boff[i >> 10];
        g_rowptr[i] = ex;
        g_cursor[i] = ex;
    }
    if (i == 0) g_rowptr[NN] = EE;
}

__global__ void k_scatter(const int* __restrict__ ei, const float* __restrict__ w) {
    int e = blockIdx.x * blockDim.x + threadIdx.x;
    if (e < EE) {
        int r = ei[e];
        int c = ei[EE + e];
        float ne = g_dinv[r] * w[e] * g_dinv[c];
        int pos = atomicAdd(g_cursor + c, 1);
        g_csr_src[pos] = r;
        g_csr_w[pos] = ne;
    }
}

// ---------------- CSR aggregation (gather, no atomics) -----------------------
template <int F, bool BIAS, bool SIG, Buf HB, Buf OB, bool HX, bool OX>
__global__ void k_agg(const float* __restrict__ hx, float* __restrict__ ox,
                      const float* __restrict__ bias) {
    constexpr int C = F / 4;
    int node = blockIdx.x * (256 / C) + threadIdx.x / C;
    int ch = threadIdx.x % C;
    if (node >= NN) return;
    const float* h = HX ? hx : bufp<HB>();
    float* out = OX ? ox : bufp<OB>();

    int beg = g_rowptr[node];
    int end = g_rowptr[node + 1];
    float s = g_nself[node];
    float4 v = __ldg((const float4*)(h + (size_t)node * F + ch * 4));
    float ax = v.x * s, ay = v.y * s, az = v.z * s, aw = v.w * s;

    for (int j = beg; j < end; j++) {
        int src = g_csr_src[j];
        float wv = g_csr_w[j];
        float4 u = __ldg((const float4*)(h + (size_t)src * F + ch * 4));
        ax += u.x * wv; ay += u.y * wv; az += u.z * wv; aw += u.w * wv;
    }
    if (BIAS) {
        float4 b = *(const float4*)(bias + ch * 4);
        ax += b.x; ay += b.y; az += b.z; aw += b.w;
    }
    if (SIG) {
        ax = 1.f / (1.f + __expf(-ax));
        ay = 1.f / (1.f + __expf(-ay));
        az = 1.f / (1.f + __expf(-az));
        aw = 1.f / (1.f + __expf(-aw));
    }
    float4 o = {ax, ay, az, aw};
    *(float4*)(out + (size_t)node * F + ch * 4) = o;
}

// ---------------- register-tiled GEMM ----------------------------------------
// C[N,OUT] = A[N,IN] @ W[IN,OUT] (+bias). 256 threads; thread tile 8x8.
// CG = OUT/8 column groups; ROWS = (256/CG)*8 rows per block.
// A read via LDG float4 (broadcast within warp), W staged whole in smem.
template <int IN, int OUT, bool BIAS, Buf AB, Buf CB>
__global__ void __launch_bounds__(256) k_gemm(const float* __restrict__ W,
                                              const float* __restrict__ bias) {
    constexpr int CG = OUT / 8;
    constexpr int RG = 256 / CG;
    constexpr int ROWS = RG * 8;
    const float* A = bufp<AB>();
    float* C = bufp<CB>();

    __shared__ float sW[IN * OUT];
    int t = threadIdx.x;
#pragma unroll
    for (int i = t; i < IN * OUT; i += 256) sW[i] = W[i];
    __syncthreads();

    int cg = t % CG;             // column group: cols [cg*8, cg*8+8)
    int rg = t / CG;             // row group: rows [rg*8, rg*8+8)
    int row0 = blockIdx.x * ROWS + rg * 8;
    if (row0 >= NN) return;

    float acc[8][8];
#pragma unroll
    for (int i = 0; i < 8; i++)
#pragma unroll
        for (int j = 0; j < 8; j++) acc[i][j] = 0.f;

    const int c0 = cg * 8;
#pragma unroll 2
    for (int k4 = 0; k4 < IN / 4; k4++) {
        float4 a[8];
#pragma unroll
        for (int i = 0; i < 8; i++) {
            int ri = row0 + i;
            if (ri >= NN) ri = NN - 1;             // clamp (store is guarded)
            a[i] = __ldg((const float4*)(A + (size_t)ri * IN) + k4);
        }
#pragma unroll
        for (int kk = 0; kk < 4; kk++) {
            const float* wr = sW + (k4 * 4 + kk) * OUT + c0;
            float4 w0 = *(const float4*)(wr);
            float4 w1 = *(const float4*)(wr + 4);
            float wv[8] = {w0.x, w0.y, w0.z, w0.w, w1.x, w1.y, w1.z, w1.w};
#pragma unroll
            for (int i = 0; i < 8; i++) {
                float av = (kk == 0) ? a[i].x : (kk == 1) ? a[i].y
                          : (kk == 2) ? a[i].z : a[i].w;
#pragma unroll
                for (int j = 0; j < 8; j++) acc[i][j] += av * wv[j];
            }
        }
    }

    float4 bv0, bv1;
    if (BIAS) {
        bv0 = *(const float4*)(bias + c0);
        bv1 = *(const float4*)(bias + c0 + 4);
    }
#pragma unroll
    for (int i = 0; i < 8; i++) {
        int ri = row0 + i;
        if (ri >= NN) break;
        float4 o0 = {acc[i][0], acc[i][1], acc[i][2], acc[i][3]};
        float4 o1 = {acc[i][4], acc[i][5], acc[i][6], acc[i][7]};
        if (BIAS) {
            o0.x += bv0.x; o0.y += bv0.y; o0.z += bv0.z; o0.w += bv0.w;
            o1.x += bv1.x; o1.y += bv1.y; o1.z += bv1.z; o1.w += bv1.w;
        }
        float* cp = C + (size_t)ri * OUT + c0;
        *(float4*)(cp) = o0;
        *(float4*)(cp + 4) = o1;
    }
}

// ---------------- launch ------------------------------------------------------
extern "C" void kernel_launch(void* const* d_in, const int* in_sizes, int n_in,
                              void* d_out, int out_size) {
    const float* x  = (const float*)d_in[0];
    const int*   ei = (const int*)d_in[1];     // int32 (JAX downcasts int64)
    const float* w  = (const float*)d_in[2];
    const float* W1 = (const float*)d_in[3];
    const float* b1 = (const float*)d_in[4];
    const float* W2 = (const float*)d_in[5];
    const float* b2 = (const float*)d_in[6];
    const float* W3 = (const float*)d_in[7];
    const float* b3 = (const float*)d_in[8];
    float* out = (float*)d_out;

    const int T = 256;
    // --- normalization + CSR build ---
    k_init<<<(NN + T - 1) / T, T>>>();
    k_deg<<<(EE + T - 1) / T, T>>>(ei, w);
    k_dinv<<<(NN + T - 1) / T, T>>>();
    k_scan1<<<NB, 1024>>>();
    k_scan2<<<1, 128>>>();
    k_finalize<<<(NN + T - 1) / T, T>>>();
    k_scatter<<<(EE + T - 1) / T, T>>>(ei, w);

    // --- Layer 1: aggregate X (width 64) -> bufA, GEMM 64->128 (+b1) -> bufB
    k_agg<64, false, false, BA, BA, true, false><<<NN * 16 / T + 1, T>>>(x, nullptr, nullptr);
    k_gemm<64, 128, true, BA, BB><<<(NN + 127) / 128, T>>>(W1, b1);

    // --- Layer 2: GEMM 128->64 (bufB->bufA), aggregate (+b2) -> bufB
    k_gemm<128, 64, false, BB, BA><<<(NN + 255) / 256, T>>>(W2, nullptr);
    k_agg<64, true, false, BA, BB, false, false><<<NN * 16 / T + 1, T>>>(nullptr, nullptr, b2);

    // --- Layer 3: GEMM 64->32 (bufB->bufA), aggregate (+b3, sigmoid) -> d_out
    k_gemm<64, 32, false, BB, BA><<<(NN + 511) / 512, T>>>(W3, nullptr);
    k_agg<32, true, true, BA, BA, false, true><<<NN * 8 / T + 1, T>>>(nullptr, out, b3);
}

// round 6
// speedup vs baseline: 3.1427x; 1.1359x over previous
#include <cuda_runtime.h>

#define NN 100000
#define EE 1600000
#define NB 98   // ceil(NN/1024)

// ---------------- scratch (static __device__ globals) ------------------------
__device__ float g_dinv[NN];
__device__ float g_nself[NN];
__device__ int   g_cnt[NN];
__device__ int   g_incl[NN];
__device__ int   g_bsum[NB];
__device__ int   g_boff[NB];
__device__ int   g_rowptr[NN + 1];
__device__ int   g_cursor[NN];
__device__ int   g_csr_src[EE];
__device__ float g_csr_w[EE];
__device__ float g_bufA[(size_t)NN * 64];
__device__ float g_bufB[(size_t)NN * 128];

enum Buf { BA, BB };
template <Buf B> __device__ __forceinline__ float* bufp() {
    return (B == BA) ? g_bufA : g_bufB;
}

// ---------------- setup ------------------------------------------------------
__global__ void k_init() {
    int i = blockIdx.x * blockDim.x + threadIdx.x;
    if (i < NN) { g_dinv[i] = 1.0f; g_cnt[i] = 0; }
}

__global__ void k_deg(const int* __restrict__ ei, const float* __restrict__ w) {
    int e = blockIdx.x * blockDim.x + threadIdx.x;
    if (e < EE) {
        int c = ei[EE + e];
        atomicAdd(g_dinv + c, w[e]);
        atomicAdd(g_cnt + c, 1);
    }
}

__global__ void k_dinv() {
    int i = blockIdx.x * blockDim.x + threadIdx.x;
    if (i < NN) {
        float d = rsqrtf(g_dinv[i]);
        g_dinv[i] = d;
        g_nself[i] = d * d;
    }
}

__global__ void k_scan1() {
    __shared__ int s[1024];
    int i = blockIdx.x * 1024 + threadIdx.x;
    int v = (i < NN) ? g_cnt[i] : 0;
    s[threadIdx.x] = v;
    __syncthreads();
    for (int d = 1; d < 1024; d <<= 1) {
        int t = (threadIdx.x >= d) ? s[threadIdx.x - d] : 0;
        __syncthreads();
        s[threadIdx.x] += t;
        __syncthreads();
    }
    if (i < NN) g_incl[i] = s[threadIdx.x];
    if (threadIdx.x == 1023) g_bsum[blockIdx.x] = s[1023];
}

__global__ void k_scan2() {
    __shared__ int s[128];
    int v = (threadIdx.x < NB) ? g_bsum[threadIdx.x] : 0;
    s[threadIdx.x] = v;
    __syncthreads();
    for (int d = 1; d < 128; d <<= 1) {
        int t = (threadIdx.x >= d) ? s[threadIdx.x - d] : 0;
        __syncthreads();
        s[threadIdx.x] += t;
        __syncthreads();
    }
    if (threadIdx.x < NB) g_boff[threadIdx.x] = s[threadIdx.x] - v;  // exclusive
}

__global__ void k_finalize() {
    int i = blockIdx.x * blockDim.x + threadIdx.x;
    if (i < NN) {
        int ex = g_incl[i] - g_cnt[i] + g_boff[i >> 10];
        g_rowptr[i] = ex;
        g_cursor[i] = ex;
    }
    if (i == 0) g_rowptr[NN] = EE;
}

__global__ void k_scatter(const int* __restrict__ ei, const float* __restrict__ w) {
    int e = blockIdx.x * blockDim.x + threadIdx.x;
    if (e < EE) {
        int r = ei[e];
        int c = ei[EE + e];
        float ne = g_dinv[r] * w[e] * g_dinv[c];
        int pos = atomicAdd(g_cursor + c, 1);
        g_csr_src[pos] = r;
        g_csr_w[pos] = ne;
    }
}

// ---------------- CSR aggregation (gather, no atomics) -----------------------
template <int F, bool BIAS, bool SIG, Buf HB, Buf OB, bool HX, bool OX>
__global__ void k_agg(const float* __restrict__ hx, float* __restrict__ ox,
                      const float* __restrict__ bias) {
    constexpr int C = F / 4;
    int node = blockIdx.x * (256 / C) + threadIdx.x / C;
    int ch = threadIdx.x % C;
    if (node >= NN) return;
    const float* h = HX ? hx : bufp<HB>();
    float* out = OX ? ox : bufp<OB>();

    int beg = g_rowptr[node];
    int end = g_rowptr[node + 1];
    float s = g_nself[node];
    float4 v = __ldg((const float4*)(h + (size_t)node * F + ch * 4));
    float ax = v.x * s, ay = v.y * s, az = v.z * s, aw = v.w * s;

    for (int j = beg; j < end; j++) {
        int src = g_csr_src[j];
        float wv = g_csr_w[j];
        float4 u = __ldg((const float4*)(h + (size_t)src * F + ch * 4));
        ax += u.x * wv; ay += u.y * wv; az += u.z * wv; aw += u.w * wv;
    }
    if (BIAS) {
        float4 b = *(const float4*)(bias + ch * 4);
        ax += b.x; ay += b.y; az += b.z; aw += b.w;
    }
    if (SIG) {
        ax = 1.f / (1.f + __expf(-ax));
        ay = 1.f / (1.f + __expf(-ay));
        az = 1.f / (1.f + __expf(-az));
        aw = 1.f / (1.f + __expf(-aw));
    }
    float4 o = {ax, ay, az, aw};
    *(float4*)(out + (size_t)node * F + ch * 4) = o;
}

// ---------------- tensor-core GEMM (3xTF32, mma.sync m16n8k8) ----------------
__device__ __forceinline__ void split_tf32(float v, unsigned& hi, unsigned& lo) {
    unsigned h;
    asm("cvt.rna.tf32.f32 %0, %1;" : "=r"(h) : "f"(v));
    float hf = __uint_as_float(h);
    float l = v - hf;
    unsigned lb;
    asm("cvt.rna.tf32.f32 %0, %1;" : "=r"(lb) : "f"(l));
    hi = h; lo = lb;
}

__device__ __forceinline__ void mma_tf32(float* c, const unsigned* a,
                                         unsigned b0, unsigned b1) {
    asm volatile(
        "mma.sync.aligned.m16n8k8.row.col.f32.tf32.tf32.f32 "
        "{%0,%1,%2,%3}, {%4,%5,%6,%7}, {%8,%9}, {%0,%1,%2,%3};\n"
        : "+f"(c[0]), "+f"(c[1]), "+f"(c[2]), "+f"(c[3])
        : "r"(a[0]), "r"(a[1]), "r"(a[2]), "r"(a[3]), "r"(b0), "r"(b1));
}

// C[N,OUT] = A[N,IN] @ W[IN,OUT] (+bias). 256 thr = 8 warps x m16 = 128 rows/blk.
// W split hi/lo into dyn smem, stride OUT+8 (conflict-free B-frag LDS).
template <int IN, int OUT, bool BIAS, Buf AB, Buf CB>
__global__ void __launch_bounds__(256) k_gemm_mma(const float* __restrict__ W,
                                                  const float* __restrict__ bias) {
    constexpr int KT = IN / 8;       // k steps
    constexpr int NT = OUT / 8;      // n tiles
    constexpr int S = OUT + 8;       // padded smem stride
    const float* A = bufp<AB>();
    float* C = bufp<CB>();

    extern __shared__ float sm[];
    float* sHi = sm;                 // [IN][S]
    float* sLo = sm + IN * S;        // [IN][S]

    int t = threadIdx.x;
    for (int i = t; i < IN * OUT; i += 256) {
        int k = i / OUT, n = i % OUT;
        unsigned hi, lo;
        split_tf32(W[i], hi, lo);
        sHi[k * S + n] = __uint_as_float(hi);
        sLo[k * S + n] = __uint_as_float(lo);
    }
    __syncthreads();

    int warp = t >> 5, lane = t & 31;
    int g = lane >> 2, tg = lane & 3;
    int row0 = blockIdx.x * 128 + warp * 16;

    float acc[NT][4];
#pragma unroll
    for (int n = 0; n < NT; n++)
#pragma unroll
        for (int j = 0; j < 4; j++) acc[n][j] = 0.f;

    int r0 = row0 + g;       if (r0 >= NN) r0 = NN - 1;
    int r1 = row0 + g + 8;   if (r1 >= NN) r1 = NN - 1;
    const float* Ar0 = A + (size_t)r0 * IN;
    const float* Ar1 = A + (size_t)r1 * IN;

#pragma unroll
    for (int k = 0; k < KT; k++) {
        // A fragment: a0=(g, 8k+tg) a1=(g+8, 8k+tg) a2=(g, 8k+tg+4) a3=(g+8, +4)
        float a0f = __ldg(Ar0 + k * 8 + tg);
        float a1f = __ldg(Ar1 + k * 8 + tg);
        float a2f = __ldg(Ar0 + k * 8 + tg + 4);
        float a3f = __ldg(Ar1 + k * 8 + tg + 4);
        unsigned ah[4], al[4];
        split_tf32(a0f, ah[0], al[0]);
        split_tf32(a1f, ah[1], al[1]);
        split_tf32(a2f, ah[2], al[2]);
        split_tf32(a3f, ah[3], al[3]);

        int kb0 = (k * 8 + tg) * S;
        int kb1 = (k * 8 + tg + 4) * S;
#pragma unroll
        for (int n = 0; n < NT; n++) {
            int nb = n * 8 + g;
            unsigned bh0 = __float_as_uint(sHi[kb0 + nb]);
            unsigned bh1 = __float_as_uint(sHi[kb1 + nb]);
            unsigned bl0 = __float_as_uint(sLo[kb0 + nb]);
            unsigned bl1 = __float_as_uint(sLo[kb1 + nb]);
            mma_tf32(acc[n], ah, bh0, bh1);   // hi*hi
            mma_tf32(acc[n], ah, bl0, bl1);   // hi*lo
            mma_tf32(acc[n], al, bh0, bh1);   // lo*hi
        }
    }

    // store: c0,c1 -> (row0+g, n*8+2tg..+1); c2,c3 -> (row0+g+8, same cols)
    int sr0 = row0 + g;
    int sr1 = row0 + g + 8;
#pragma unroll
    for (int n = 0; n < NT; n++) {
        int c0 = n * 8 + tg * 2;
        float b0 = 0.f, b1 = 0.f;
        if (BIAS) { b0 = bias[c0]; b1 = bias[c0 + 1]; }
        if (sr0 < NN) {
            float2 o = {acc[n][0] + b0, acc[n][1] + b1};
            *(float2*)(C + (size_t)sr0 * OUT + c0) = o;
        }
        if (sr1 < NN) {
            float2 o = {acc[n][2] + b0, acc[n][3] + b1};
            *(float2*)(C + (size_t)sr1 * OUT + c0) = o;
        }
    }
}

// ---------------- launch ------------------------------------------------------
extern "C" void kernel_launch(void* const* d_in, const int* in_sizes, int n_in,
                              void* d_out, int out_size) {
    const float* x  = (const float*)d_in[0];
    const int*   ei = (const int*)d_in[1];     // int32 (JAX downcasts int64)
    const float* w  = (const float*)d_in[2];
    const float* W1 = (const float*)d_in[3];
    const float* b1 = (const float*)d_in[4];
    const float* W2 = (const float*)d_in[5];
    const float* b2 = (const float*)d_in[6];
    const float* W3 = (const float*)d_in[7];
    const float* b3 = (const float*)d_in[8];
    float* out = (float*)d_out;

    const int T = 256;
    const int GB = (NN + 127) / 128;   // gemm grid

    // dyn smem sizes: IN*(OUT+8)*2 floats
    const int S1 = 64  * (128 + 8) * 2 * 4;
    const int S2 = 128 * (64 + 8)  * 2 * 4;
    const int S3 = 64  * (32 + 8)  * 2 * 4;
    cudaFuncSetAttribute(k_gemm_mma<64, 128, true,  BA, BB>,
                         cudaFuncAttributeMaxDynamicSharedMemorySize, S1);
    cudaFuncSetAttribute(k_gemm_mma<128, 64, false, BB, BA>,
                         cudaFuncAttributeMaxDynamicSharedMemorySize, S2);
    cudaFuncSetAttribute(k_gemm_mma<64, 32, false,  BB, BA>,
                         cudaFuncAttributeMaxDynamicSharedMemorySize, S3);

    // --- normalization + CSR build ---
    k_init<<<(NN + T - 1) / T, T>>>();
    k_deg<<<(EE + T - 1) / T, T>>>(ei, w);
    k_dinv<<<(NN + T - 1) / T, T>>>();
    k_scan1<<<NB, 1024>>>();
    k_scan2<<<1, 128>>>();
    k_finalize<<<(NN + T - 1) / T, T>>>();
    k_scatter<<<(EE + T - 1) / T, T>>>(ei, w);

    // --- Layer 1: aggregate X (width 64) -> bufA, GEMM 64->128 (+b1) -> bufB
    k_agg<64, false, false, BA, BA, true, false><<<NN * 16 / T + 1, T>>>(x, nullptr, nullptr);
    k_gemm_mma<64, 128, true, BA, BB><<<GB, T, S1>>>(W1, b1);

    // --- Layer 2: GEMM 128->64 (bufB->bufA), aggregate (+b2) -> bufB
    k_gemm_mma<128, 64, false, BB, BA><<<GB, T, S2>>>(W2, nullptr);
    k_agg<64, true, false, BA, BB, false, false><<<NN * 16 / T + 1, T>>>(nullptr, nullptr, b2);

    // --- Layer 3: GEMM 64->32 (bufB->bufA), aggregate (+b3, sigmoid) -> d_out
    k_gemm_mma<64, 32, false, BB, BA><<<GB, T, S3>>>(W3, nullptr);
    k_agg<32, true, true, BA, BA, false, true><<<NN * 8 / T + 1, T>>>(nullptr, out, b3);
}

// round 9
// speedup vs baseline: 3.7656x; 1.1982x over previous
#include <cuda_runtime.h>

#define NN 100000
#define EE 1600000
#define NB 98   // ceil(NN/1024)

// ---------------- scratch (static __device__ globals) ------------------------
__device__ float g_dinv[NN];
__device__ float g_nself[NN];
__device__ int   g_cnt[NN];
__device__ int   g_incl[NN];
__device__ int   g_bsum[NB];
__device__ int   g_boff[NB];
__device__ int   g_rowptr[NN + 1];
__device__ int   g_cursor[NN];
__device__ int   g_csr_src[EE];
__device__ float g_csr_w[EE];
__device__ float g_a1[NN];            // A_hat @ ones
__device__ float g_a2[NN];            // A_hat^2 @ ones
__device__ float g_Wc[64 * 32];       // W1 @ W2 @ W3
__device__ float g_bt1[32];           // b1 @ W2 @ W3
__device__ float g_bt2[32];           // b2 @ W3
__device__ float g_bufA[(size_t)NN * 32];
__device__ float g_bufB[(size_t)NN * 32];

enum Buf { BA, BB };
template <Buf B> __device__ __forceinline__ float* bufp() {
    return (B == BA) ? g_bufA : g_bufB;
}

// ---------------- setup ------------------------------------------------------
__global__ void k_init() {
    int i = blockIdx.x * blockDim.x + threadIdx.x;
    if (i < NN) { g_dinv[i] = 1.0f; g_cnt[i] = 0; }
}

__global__ void k_deg(const int* __restrict__ ei, const float* __restrict__ w) {
    int e = blockIdx.x * blockDim.x + threadIdx.x;
    if (e < EE) {
        int c = ei[EE + e];
        atomicAdd(g_dinv + c, w[e]);
        atomicAdd(g_cnt + c, 1);
    }
}

__global__ void k_dinv() {
    int i = blockIdx.x * blockDim.x + threadIdx.x;
    if (i < NN) {
        float d = rsqrtf(g_dinv[i]);
        g_dinv[i] = d;
        g_nself[i] = d * d;
    }
}

__global__ void __launch_bounds__(1024) k_scan1() {
    __shared__ int s[1024];
    int i = blockIdx.x * 1024 + threadIdx.x;
    int v = (i < NN) ? g_cnt[i] : 0;
    s[threadIdx.x] = v;
    __syncthreads();
    for (int d = 1; d < 1024; d <<= 1) {
        int t = (threadIdx.x >= d) ? s[threadIdx.x - d] : 0;
        __syncthreads();
        s[threadIdx.x] += t;
        __syncthreads();
    }
    if (i < NN) g_incl[i] = s[threadIdx.x];
    if (threadIdx.x == 1023) g_bsum[blockIdx.x] = s[1023];
}

__global__ void k_scan2() {
    __shared__ int s[128];
    int v = (threadIdx.x < NB) ? g_bsum[threadIdx.x] : 0;
    s[threadIdx.x] = v;
    __syncthreads();
    for (int d = 1; d < 128; d <<= 1) {
        int t = (threadIdx.x >= d) ? s[threadIdx.x - d] : 0;
        __syncthreads();
        s[threadIdx.x] += t;
        __syncthreads();
    }
    if (threadIdx.x < NB) g_boff[threadIdx.x] = s[threadIdx.x] - v;  // exclusive
}

__global__ void k_finalize() {
    int i = blockIdx.x * blockDim.x + threadIdx.x;
    if (i < NN) {
        int ex = g_incl[i] - g_cnt[i] + g_boff[i >> 10];
        g_rowptr[i] = ex;
        g_cursor[i] = ex;
    }
    if (i == 0) g_rowptr[NN] = EE;
}

__global__ void k_scatter(const int* __restrict__ ei, const float* __restrict__ w) {
    int e = blockIdx.x * blockDim.x + threadIdx.x;
    if (e < EE) {
        int r = ei[e];
        int c = ei[EE + e];
        float ne = g_dinv[r] * w[e] * g_dinv[c];
        int pos = atomicAdd(g_cursor + c, 1);
        g_csr_src[pos] = r;
        g_csr_w[pos] = ne;
    }
}

// ---------------- collapsed weights: Wc = W1@W2@W3, bt1 = b1@W2@W3, bt2 = b2@W3
__global__ void __launch_bounds__(256) k_wc(
        const float* __restrict__ W1, const float* __restrict__ W2,
        const float* __restrict__ W3, const float* __restrict__ b1,
        const float* __restrict__ b2) {
    __shared__ float sW12[64 * 64];
    __shared__ float sbw[64];
    int t = threadIdx.x;   // 256
    for (int i = t; i < 64 * 64; i += 256) {
        int r = i >> 6, c = i & 63;
        float s = 0.f;
        for (int k = 0; k < 128; k++) s += W1[r * 128 + k] * W2[k * 64 + c];
        sW12[i] = s;
    }
    if (t < 64) {
        float s = 0.f;
        for (int k = 0; k < 128; k++) s += b1[k] * W2[k * 64 + t];
        sbw[t] = s;
    }
    __syncthreads();
    for (int i = t; i < 64 * 32; i += 256) {
        int r = i >> 5, c = i & 31;
        float s = 0.f;
        for (int k = 0; k < 64; k++) s += sW12[r * 64 + k] * W3[k * 32 + c];
        g_Wc[i] = s;
    }
    if (t < 32) {
        float s1 = 0.f, s2 = 0.f;
        for (int k = 0; k < 64; k++) {
            s1 += sbw[k] * W3[k * 32 + t];
            s2 += b2[k] * W3[k * 32 + t];
        }
        g_bt1[t] = s1;
        g_bt2[t] = s2;
    }
}

// ---------------- a1 = A_hat @ 1, a2 = A_hat @ a1 -----------------------------
__global__ void k_a1() {
    int i = blockIdx.x * blockDim.x + threadIdx.x;
    if (i < NN) {
        int beg = g_rowptr[i], end = g_rowptr[i + 1];
        float s = g_nself[i];
        for (int j = beg; j < end; j++) s += g_csr_w[j];
        g_a1[i] = s;
    }
}

__global__ void k_a2() {
    int i = blockIdx.x * blockDim.x + threadIdx.x;
    if (i < NN) {
        int beg = g_rowptr[i], end = g_rowptr[i + 1];
        float s = g_nself[i] * g_a1[i];
        for (int j = beg; j < end; j++) s += g_csr_w[j] * g_a1[g_csr_src[j]];
        g_a2[i] = s;
    }
}

// ---------------- width-32 CSR aggregation (gather) ---------------------------
// t[i] = nself[i]*h[i] + sum_in w_e h[src]; FINAL adds bias terms + sigmoid.
template <bool FINAL, Buf HB, Buf OB>
__global__ void __launch_bounds__(256) k_agg32(float* __restrict__ ox,
                                               const float* __restrict__ b3) {
    int node = blockIdx.x * 32 + (threadIdx.x >> 3);
    int ch = threadIdx.x & 7;
    if (node >= NN) return;
    const float* h = bufp<HB>();
    float* out = FINAL ? ox : bufp<OB>();

    int beg = g_rowptr[node];
    int end = g_rowptr[node + 1];
    float s = g_nself[node];
    float4 v = __ldg((const float4*)(h + (size_t)node * 32 + ch * 4));
    float ax = v.x * s, ay = v.y * s, az = v.z * s, aw = v.w * s;

    int j = beg;
    for (; j + 1 < end; j += 2) {
        int s0 = g_csr_src[j];
        int s1 = g_csr_src[j + 1];
        float w0 = g_csr_w[j];
        float w1 = g_csr_w[j + 1];
        float4 u0 = __ldg((const float4*)(h + (size_t)s0 * 32 + ch * 4));
        float4 u1 = __ldg((const float4*)(h + (size_t)s1 * 32 + ch * 4));
        ax += u0.x * w0; ay += u0.y * w0; az += u0.z * w0; aw += u0.w * w0;
        ax += u1.x * w1; ay += u1.y * w1; az += u1.z * w1; aw += u1.w * w1;
    }
    if (j < end) {
        int s0 = g_csr_src[j];
        float w0 = g_csr_w[j];
        float4 u0 = __ldg((const float4*)(h + (size_t)s0 * 32 + ch * 4));
        ax += u0.x * w0; ay += u0.y * w0; az += u0.z * w0; aw += u0.w * w0;
    }

    if (FINAL) {
        float a1v = g_a1[node];
        float a2v = g_a2[node];
        float4 t1 = *(const float4*)(g_bt1 + ch * 4);
        float4 t2 = *(const float4*)(g_bt2 + ch * 4);
        float4 b = *(const float4*)(b3 + ch * 4);
        ax += a2v * t1.x + a1v * t2.x + b.x;
        ay += a2v * t1.y + a1v * t2.y + b.y;
        az += a2v * t1.z + a1v * t2.z + b.z;
        aw += a2v * t1.w + a1v * t2.w + b.w;
        ax = 1.f / (1.f + __expf(-ax));
        ay = 1.f / (1.f + __expf(-ay));
        az = 1.f / (1.f + __expf(-az));
        aw = 1.f / (1.f + __expf(-aw));
    }
    float4 o = {ax, ay, az, aw};
    *(float4*)(out + (size_t)node * 32 + ch * 4) = o;
}

// ---------------- tensor-core GEMM (3xTF32, mma.sync m16n8k8) ----------------
__device__ __forceinline__ void split_tf32(float v, unsigned& hi, unsigned& lo) {
    unsigned h;
    asm("cvt.rna.tf32.f32 %0, %1;" : "=r"(h) : "f"(v));
    float hf = __uint_as_float(h);
    float l = v - hf;
    unsigned lb;
    asm("cvt.rna.tf32.f32 %0, %1;" : "=r"(lb) : "f"(l));
    hi = h; lo = lb;
}

__device__ __forceinline__ void mma_tf32(float* c, const unsigned* a,
                                         unsigned b0, unsigned b1) {
    asm volatile(
        "mma.sync.aligned.m16n8k8.row.col.f32.tf32.tf32.f32 "
        "{%0,%1,%2,%3}, {%4,%5,%6,%7}, {%8,%9}, {%0,%1,%2,%3};\n"
        : "+f"(c[0]), "+f"(c[1]), "+f"(c[2]), "+f"(c[3])
        : "r"(a[0]), "r"(a[1]), "r"(a[2]), "r"(a[3]), "r"(b0), "r"(b1));
}

// C[N,32] = A[N,64] @ Wc[64,32]. 256 thr = 8 warps x m16 = 128 rows/block.
__global__ void __launch_bounds__(256) k_gemm_xc(const float* __restrict__ A) {
    constexpr int IN = 64, OUT = 32;
    constexpr int KT = IN / 8, NT = OUT / 8, S = OUT + 8;
    float* C = g_bufA;

    __shared__ float sHi[IN * S];
    __shared__ float sLo[IN * S];

    int t = threadIdx.x;
    for (int i = t; i < IN * OUT; i += 256) {
        int k = i / OUT, n = i % OUT;
        unsigned hi, lo;
        split_tf32(g_Wc[i], hi, lo);
        sHi[k * S + n] = __uint_as_float(hi);
        sLo[k * S + n] = __uint_as_float(lo);
    }
    __syncthreads();

    int warp = t >> 5, lane = t & 31;
    int g = lane >> 2, tg = lane & 3;
    int row0 = blockIdx.x * 128 + warp * 16;

    float acc[NT][4];
#pragma unroll
    for (int n = 0; n < NT; n++)
#pragma unroll
        for (int j = 0; j < 4; j++) acc[n][j] = 0.f;

    int r0 = row0 + g;       if (r0 >= NN) r0 = NN - 1;
    int r1 = row0 + g + 8;   if (r1 >= NN) r1 = NN - 1;
    const float* Ar0 = A + (size_t)r0 * IN;
    const float* Ar1 = A + (size_t)r1 * IN;

#pragma unroll
    for (int k = 0; k < KT; k++) {
        float a0f = __ldg(Ar0 + k * 8 + tg);
        float a1f = __ldg(Ar1 + k * 8 + tg);
        float a2f = __ldg(Ar0 + k * 8 + tg + 4);
        float a3f = __ldg(Ar1 + k * 8 + tg + 4);
        unsigned ah[4], al[4];
        split_tf32(a0f, ah[0], al[0]);
        split_tf32(a1f, ah[1], al[1]);
        split_tf32(a2f, ah[2], al[2]);
        split_tf32(a3f, ah[3], al[3]);

        int kb0 = (k * 8 + tg) * S;
        int kb1 = (k * 8 + tg + 4) * S;
#pragma unroll
        for (int n = 0; n < NT; n++) {
            int nb = n * 8 + g;
            unsigned bh0 = __float_as_uint(sHi[kb0 + nb]);
            unsigned bh1 = __float_as_uint(sHi[kb1 + nb]);
            unsigned bl0 = __float_as_uint(sLo[kb0 + nb]);
            unsigned bl1 = __float_as_uint(sLo[kb1 + nb]);
            mma_tf32(acc[n], ah, bh0, bh1);
            mma_tf32(acc[n], ah, bl0, bl1);
            mma_tf32(acc[n], al, bh0, bh1);
        }
    }

    int sr0 = row0 + g;
    int sr1 = row0 + g + 8;
#pragma unroll
    for (int n = 0; n < NT; n++) {
        int c0 = n * 8 + tg * 2;
        if (sr0 < NN) {
            float2 o = {acc[n][0], acc[n][1]};
            *(float2*)(C + (size_t)sr0 * OUT + c0) = o;
        }
        if (sr1 < NN) {
            float2 o = {acc[n][2], acc[n][3]};
            *(float2*)(C + (size_t)sr1 * OUT + c0) = o;
        }
    }
}

// ---------------- launch ------------------------------------------------------
extern "C" void kernel_launch(void* const* d_in, const int* in_sizes, int n_in,
                              void* d_out, int out_size) {
    const float* x  = (const float*)d_in[0];
    const int*   ei = (const int*)d_in[1];     // int32 (JAX downcasts int64)
    const float* w  = (const float*)d_in[2];
    const float* W1 = (const float*)d_in[3];
    const float* b1 = (const float*)d_in[4];
    const float* W2 = (const float*)d_in[5];
    const float* b2 = (const float*)d_in[6];
    const float* W3 = (const float*)d_in[7];
    const float* b3 = (const float*)d_in[8];
    float* out = (float*)d_out;

    const int T = 256;
    // --- normalization + CSR build ---
    k_init<<<(NN + T - 1) / T, T>>>();
    k_deg<<<(EE + T - 1) / T, T>>>(ei, w);
    k_dinv<<<(NN + T - 1) / T, T>>>();
    k_scan1<<<NB, 1024>>>();
    k_scan2<<<1, 128>>>();
    k_finalize<<<(NN + T - 1) / T, T>>>();
    k_scatter<<<(EE + T - 1) / T, T>>>(ei, w);

    // --- collapsed weights + bias vectors + degree vectors ---
    k_wc<<<1, 256>>>(W1, W2, W3, b1, b2);
    k_a1<<<(NN + T - 1) / T, T>>>();
    k_a2<<<(NN + T - 1) / T, T>>>();

    // --- xc = x @ Wc  -> bufA ---
    k_gemm_xc<<<(NN + 127) / 128, T>>>(x);

    // --- three width-32 aggregations ---
    const int GA = (NN + 31) / 32;
    k_agg32<false, BA, BB><<<GA, T>>>(nullptr, nullptr);   // t1 -> bufB
    k_agg32<false, BB, BA><<<GA, T>>>(nullptr, nullptr);   // t2 -> bufA
    k_agg32<true,  BA, BA><<<GA, T>>>(out, b3);            // t3 (+bias,sigmoid) -> out
}